// round 1
// baseline (speedup 1.0000x reference)
#include <cuda_runtime.h>
#include <cuda_bf16.h>

// out[i] = 0.1 * x[i] * sum_j A[i][j] * (1 - x[j])
// HBM-bound fp32 matvec: stream A (1 GiB) once, (1-x) cached in SMEM.

#define WARPS_PER_BLOCK 8
#define THREADS (WARPS_PER_BLOCK * 32)

__global__ void __launch_bounds__(THREADS)
epidemic_matvec_kernel(const float* __restrict__ x,
                       const float* __restrict__ A,
                       float* __restrict__ out,
                       int n)
{
    extern __shared__ float xs[];          // holds (1 - x), n floats
    const int tid = threadIdx.x;
    const int nv = n >> 2;                 // number of float4 chunks in a row

    // Cooperatively stage (1 - x) into shared memory, vectorized.
    const float4* __restrict__ x4 = reinterpret_cast<const float4*>(x);
    float4* xs4 = reinterpret_cast<float4*>(xs);
    for (int i = tid; i < nv; i += THREADS) {
        float4 v = x4[i];
        xs4[i] = make_float4(1.0f - v.x, 1.0f - v.y, 1.0f - v.z, 1.0f - v.w);
    }
    // scalar tail of x (n not multiple of 4)
    for (int i = (nv << 2) + tid; i < n; i += THREADS) {
        xs[i] = 1.0f - x[i];
    }
    __syncthreads();

    const int warp = tid >> 5;
    const int lane = tid & 31;
    const int row  = blockIdx.x * WARPS_PER_BLOCK + warp;
    if (row >= n) return;

    const float4* __restrict__ Arow =
        reinterpret_cast<const float4*>(A + (size_t)row * (size_t)n);

    float s0 = 0.0f, s1 = 0.0f, s2 = 0.0f, s3 = 0.0f;

    // Main loop: 4 independent LDG.128 per iteration per lane (MLP=4),
    // warp covers 128 float4 = 512 floats per iteration.
    int k = lane;
    for (; k + 96 < nv; k += 128) {
        float4 a0 = Arow[k];
        float4 a1 = Arow[k + 32];
        float4 a2 = Arow[k + 64];
        float4 a3 = Arow[k + 96];
        float4 b0 = xs4[k];
        float4 b1 = xs4[k + 32];
        float4 b2 = xs4[k + 64];
        float4 b3 = xs4[k + 96];
        s0 += a0.x * b0.x + a0.y * b0.y + a0.z * b0.z + a0.w * b0.w;
        s1 += a1.x * b1.x + a1.y * b1.y + a1.z * b1.z + a1.w * b1.w;
        s2 += a2.x * b2.x + a2.y * b2.y + a2.z * b2.z + a2.w * b2.w;
        s3 += a3.x * b3.x + a3.y * b3.y + a3.z * b3.z + a3.w * b3.w;
    }
    // float4 tail
    for (; k < nv; k += 32) {
        float4 a0 = Arow[k];
        float4 b0 = xs4[k];
        s0 += a0.x * b0.x + a0.y * b0.y + a0.z * b0.z + a0.w * b0.w;
    }
    // scalar tail (n not multiple of 4)
    const float* __restrict__ Arow_s = A + (size_t)row * (size_t)n;
    for (int j = (nv << 2) + lane; j < n; j += 32) {
        s0 += Arow_s[j] * xs[j];
    }

    float sum = (s0 + s1) + (s2 + s3);
    // warp reduction
    #pragma unroll
    for (int off = 16; off > 0; off >>= 1)
        sum += __shfl_xor_sync(0xFFFFFFFFu, sum, off);

    if (lane == 0) {
        out[row] = 0.1f * x[row] * sum;
    }
}

extern "C" void kernel_launch(void* const* d_in, const int* in_sizes, int n_in,
                              void* d_out, int out_size)
{
    // metadata order: t (unused), x [n], A [n*n]
    const float* x = (const float*)d_in[1];
    const float* A = (const float*)d_in[2];
    float* out     = (float*)d_out;
    const int n    = in_sizes[1];

    const size_t smem = (size_t)n * sizeof(float);   // 64 KB for n=16384
    cudaFuncSetAttribute(epidemic_matvec_kernel,
                         cudaFuncAttributeMaxDynamicSharedMemorySize,
                         (int)smem);

    const int blocks = (n + WARPS_PER_BLOCK - 1) / WARPS_PER_BLOCK;
    epidemic_matvec_kernel<<<blocks, THREADS, smem>>>(x, A, out, n);
}

// round 2
// speedup vs baseline: 1.0998x; 1.0998x over previous
#include <cuda_runtime.h>
#include <cuda_bf16.h>

// out[i] = 0.1 * x[i] * sum_j A[i][j] * (1 - x[j])
// HBM-bound fp32 matvec. Stream A (1 GiB) once via __ldcs (evict-first),
// y = (1 - x) precomputed into a device scratch array and served from L1/L2.
// No shared memory -> occupancy limited only by registers (~44 warps/SM).

#define WARPS_PER_BLOCK 8
#define THREADS (WARPS_PER_BLOCK * 32)
#define MAX_N 32768

__device__ float g_y[MAX_N];   // holds (1 - x)

__global__ void prep_y_kernel(const float* __restrict__ x, int n)
{
    int i = blockIdx.x * blockDim.x + threadIdx.x;
    if (i < n) g_y[i] = 1.0f - x[i];
}

__global__ void __launch_bounds__(THREADS)
epidemic_matvec_kernel(const float* __restrict__ x,
                       const float* __restrict__ A,
                       float* __restrict__ out,
                       int n)
{
    const int tid  = threadIdx.x;
    const int warp = tid >> 5;
    const int lane = tid & 31;
    const int row  = blockIdx.x * WARPS_PER_BLOCK + warp;
    if (row >= n) return;

    const int nv = n >> 2;  // float4 chunks per row
    const float4* __restrict__ Arow =
        reinterpret_cast<const float4*>(A + (size_t)row * (size_t)n);
    const float4* __restrict__ y4 = reinterpret_cast<const float4*>(g_y);

    float s0 = 0.0f, s1 = 0.0f, s2 = 0.0f, s3 = 0.0f;

    int k = lane;
    // Main loop: front-batch 4 independent streaming LDG.128 on A (MLP=4),
    // then 4 L1-hit loads on y. Warp covers 512 floats / iteration.
    for (; k + 96 < nv; k += 128) {
        float4 a0 = __ldcs(&Arow[k]);
        float4 a1 = __ldcs(&Arow[k + 32]);
        float4 a2 = __ldcs(&Arow[k + 64]);
        float4 a3 = __ldcs(&Arow[k + 96]);
        float4 b0 = y4[k];
        float4 b1 = y4[k + 32];
        float4 b2 = y4[k + 64];
        float4 b3 = y4[k + 96];
        s0 += a0.x * b0.x + a0.y * b0.y + a0.z * b0.z + a0.w * b0.w;
        s1 += a1.x * b1.x + a1.y * b1.y + a1.z * b1.z + a1.w * b1.w;
        s2 += a2.x * b2.x + a2.y * b2.y + a2.z * b2.z + a2.w * b2.w;
        s3 += a3.x * b3.x + a3.y * b3.y + a3.z * b3.z + a3.w * b3.w;
    }
    // float4 tail
    for (; k < nv; k += 32) {
        float4 a0 = __ldcs(&Arow[k]);
        float4 b0 = y4[k];
        s0 += a0.x * b0.x + a0.y * b0.y + a0.z * b0.z + a0.w * b0.w;
    }
    // scalar tail (n not multiple of 4)
    const float* __restrict__ Arow_s = A + (size_t)row * (size_t)n;
    for (int j = (nv << 2) + lane; j < n; j += 32) {
        s0 += Arow_s[j] * g_y[j];
    }

    float sum = (s0 + s1) + (s2 + s3);
    #pragma unroll
    for (int off = 16; off > 0; off >>= 1)
        sum += __shfl_xor_sync(0xFFFFFFFFu, sum, off);

    if (lane == 0) {
        out[row] = 0.1f * x[row] * sum;
    }
}

extern "C" void kernel_launch(void* const* d_in, const int* in_sizes, int n_in,
                              void* d_out, int out_size)
{
    // metadata order: t (unused), x [n], A [n*n]
    const float* x = (const float*)d_in[1];
    const float* A = (const float*)d_in[2];
    float* out     = (float*)d_out;
    const int n    = in_sizes[1];

    prep_y_kernel<<<(n + 255) / 256, 256>>>(x, n);

    const int blocks = (n + WARPS_PER_BLOCK - 1) / WARPS_PER_BLOCK;
    epidemic_matvec_kernel<<<blocks, THREADS>>>(x, A, out, n);
}

// round 3
// speedup vs baseline: 1.1221x; 1.0203x over previous
#include <cuda_runtime.h>
#include <cuda_bf16.h>

// out[i] = 0.1 * x[i] * sum_j A[i][j] * (1 - x[j])
// Single-kernel HBM-bound fp32 matvec. A (1 GiB) streamed once with
// evict-first LDG.128, x read inline (L1-resident, 64 KB) and (1-x)
// computed in registers. Warp-per-row, MLP=4.

#define WARPS_PER_BLOCK 8
#define THREADS (WARPS_PER_BLOCK * 32)

__global__ void __launch_bounds__(THREADS)
epidemic_matvec_kernel(const float* __restrict__ x,
                       const float* __restrict__ A,
                       float* __restrict__ out,
                       int n)
{
    const int tid  = threadIdx.x;
    const int warp = tid >> 5;
    const int lane = tid & 31;
    const int row  = blockIdx.x * WARPS_PER_BLOCK + warp;
    if (row >= n) return;

    const int nv = n >> 2;  // float4 chunks per row
    const float4* __restrict__ Arow =
        reinterpret_cast<const float4*>(A + (size_t)row * (size_t)n);
    const float4* __restrict__ x4 = reinterpret_cast<const float4*>(x);

    float s0 = 0.0f, s1 = 0.0f, s2 = 0.0f, s3 = 0.0f;

    int k = lane;
    // Front-batch 4 independent streaming LDG.128 on A (MLP=4), then 4
    // L1-hit loads on x. Warp covers 512 floats / iteration.
    for (; k + 96 < nv; k += 128) {
        float4 a0 = __ldcs(&Arow[k]);
        float4 a1 = __ldcs(&Arow[k + 32]);
        float4 a2 = __ldcs(&Arow[k + 64]);
        float4 a3 = __ldcs(&Arow[k + 96]);
        float4 b0 = x4[k];
        float4 b1 = x4[k + 32];
        float4 b2 = x4[k + 64];
        float4 b3 = x4[k + 96];
        s0 += a0.x * (1.0f - b0.x) + a0.y * (1.0f - b0.y)
            + a0.z * (1.0f - b0.z) + a0.w * (1.0f - b0.w);
        s1 += a1.x * (1.0f - b1.x) + a1.y * (1.0f - b1.y)
            + a1.z * (1.0f - b1.z) + a1.w * (1.0f - b1.w);
        s2 += a2.x * (1.0f - b2.x) + a2.y * (1.0f - b2.y)
            + a2.z * (1.0f - b2.z) + a2.w * (1.0f - b2.w);
        s3 += a3.x * (1.0f - b3.x) + a3.y * (1.0f - b3.y)
            + a3.z * (1.0f - b3.z) + a3.w * (1.0f - b3.w);
    }
    // float4 tail
    for (; k < nv; k += 32) {
        float4 a0 = __ldcs(&Arow[k]);
        float4 b0 = x4[k];
        s0 += a0.x * (1.0f - b0.x) + a0.y * (1.0f - b0.y)
            + a0.z * (1.0f - b0.z) + a0.w * (1.0f - b0.w);
    }
    // scalar tail (n not multiple of 4)
    const float* __restrict__ Arow_s = A + (size_t)row * (size_t)n;
    for (int j = (nv << 2) + lane; j < n; j += 32) {
        s0 += Arow_s[j] * (1.0f - x[j]);
    }

    float sum = (s0 + s1) + (s2 + s3);
    #pragma unroll
    for (int off = 16; off > 0; off >>= 1)
        sum += __shfl_xor_sync(0xFFFFFFFFu, sum, off);

    if (lane == 0) {
        out[row] = 0.1f * x[row] * sum;
    }
}

extern "C" void kernel_launch(void* const* d_in, const int* in_sizes, int n_in,
                              void* d_out, int out_size)
{
    // metadata order: t (unused), x [n], A [n*n]
    const float* x = (const float*)d_in[1];
    const float* A = (const float*)d_in[2];
    float* out     = (float*)d_out;
    const int n    = in_sizes[1];

    const int blocks = (n + WARPS_PER_BLOCK - 1) / WARPS_PER_BLOCK;
    epidemic_matvec_kernel<<<blocks, THREADS>>>(x, A, out, n);
}